// round 5
// baseline (speedup 1.0000x reference)
#include <cuda_runtime.h>
#include <cuda_bf16.h>
#include <math.h>

// ---------------------------------------------------------------------------
// Problem constants
// ---------------------------------------------------------------------------
#define N_TOKS   2048
#define HIDDEN   5120
#define HEAD_DIM 128
#define HQ       40
#define HKV      8
#define NUM_MOD  3
#define Q_SIZE   5120           // HQ * HEAD_DIM
#define KV_SIZE  1024           // HKV * HEAD_DIM
#define GATE_N   40
#define QKV_OUT  7208           // Q_SIZE + 2*KV_SIZE + GATE_N
#define NPAD     2304           // max padded sorted rows (segments 128-aligned)
#define MROWS    (5 * NPAD)     // q-rows per kv head (group size 5) = 11520

// ---------------------------------------------------------------------------
// Scratch (static device globals; total ~335 MB)
// ---------------------------------------------------------------------------
__device__ float g_hnorm[(size_t)NPAD * HIDDEN];           // 47 MB
__device__ float g_qkv[(size_t)NPAD * QKV_OUT];            // 66 MB
__device__ float g_q[(size_t)HQ * NPAD * HEAD_DIM];        // 47 MB  [hq][r][d], hq = kv*5+g
__device__ float g_k[(size_t)HKV * NPAD * HEAD_DIM];       // 9.4 MB [kv][r][d]
__device__ float g_vt[(size_t)HKV * HEAD_DIM * NPAD];      // 9.4 MB [kv][d][r]  (transposed)
__device__ float g_s[(size_t)MROWS * NPAD];                // 106 MB, reused per kv head
__device__ float g_o[(size_t)NPAD * Q_SIZE];               // 47 MB
__device__ float g_gate[NPAD * HQ];
__device__ int   g_rowMod[NPAD];
__device__ int   g_valid[NPAD];
__device__ int   g_srcTok[NPAD];
__device__ int   g_segStart[NUM_MOD + 1];
__device__ int   g_is64;

// Dtype-robust modality read (mids may be int32 or int64; detected at runtime).
__device__ __forceinline__ int getMid(const int* raw, int i, int is64) {
    return is64 ? (int)(reinterpret_cast<const long long*>(raw)[i]) : raw[i];
}

// ---------------------------------------------------------------------------
// Metadata kernels: deterministic modality sort (segments 128-aligned)
// ---------------------------------------------------------------------------
__global__ void k_meta1(const int* __restrict__ midsRaw) {
    __shared__ int cnt[NUM_MOD];
    __shared__ int sstart[NUM_MOD + 1];
    __shared__ int oddNZ;
    int tid = threadIdx.x;
    if (tid == 0) oddNZ = 0;
    if (tid < NUM_MOD) cnt[tid] = 0;
    __syncthreads();
    // int64 data has zero high-words at odd int32 positions; int32 data doesn't.
    for (int i = tid; i < N_TOKS / 2; i += blockDim.x)
        if (midsRaw[2 * i + 1] != 0) atomicExch(&oddNZ, 1);
    __syncthreads();
    int is64 = (oddNZ == 0);
    if (tid == 0) g_is64 = is64;

    for (int i = tid; i < N_TOKS; i += blockDim.x)
        atomicAdd(&cnt[getMid(midsRaw, i, is64)], 1);
    __syncthreads();
    if (tid == 0) {
        int s = 0;
        for (int m = 0; m < NUM_MOD; m++) {
            sstart[m] = s;
            g_segStart[m] = s;
            s += (cnt[m] + 127) & ~127;
        }
        sstart[NUM_MOD] = s;
        g_segStart[NUM_MOD] = s;
    }
    __syncthreads();
    for (int r = tid; r < NPAD; r += blockDim.x) {
        int mod = 0;
        if (r >= sstart[1]) mod = 1;
        if (r >= sstart[2]) mod = 2;
        if (r >= sstart[3]) mod = 0;   // tail beyond actual padded length
        g_rowMod[r] = mod;
        g_valid[r]  = 0;
        g_srcTok[r] = 0;
    }
}

// Deterministic rank: token i's slot = segStart[m] + #{j<i : mid[j]==m}
__global__ void k_meta2(const int* __restrict__ midsRaw) {
    int i = blockIdx.x * blockDim.x + threadIdx.x;
    if (i >= N_TOKS) return;
    int is64 = g_is64;
    int m = getMid(midsRaw, i, is64);
    int rank = 0;
    for (int j = 0; j < i; j++) rank += (getMid(midsRaw, j, is64) == m);
    int pos = g_segStart[m] + rank;
    g_srcTok[pos] = i;
    g_valid[pos]  = 1;
}

// ---------------------------------------------------------------------------
// Pre-norm RMSNorm + gather into sorted order (pads -> zeros)
// ---------------------------------------------------------------------------
__global__ void k_norm(const float* __restrict__ hidden,
                       const float* __restrict__ pnw) {
    int r = blockIdx.x, tid = threadIdx.x;
    int vld = g_valid[r];
    int src = g_srcTok[r];
    int mod = g_rowMod[r];
    const float4* x   = reinterpret_cast<const float4*>(hidden + (size_t)src * HIDDEN);
    const float4* w   = reinterpret_cast<const float4*>(pnw + mod * HIDDEN);
    float4*       out = reinterpret_cast<float4*>(g_hnorm + (size_t)r * HIDDEN);

    float ss = 0.f;
    if (vld) {
        for (int i = tid; i < HIDDEN / 4; i += blockDim.x) {
            float4 v = x[i];
            ss += v.x * v.x + v.y * v.y + v.z * v.z + v.w * v.w;
        }
    }
    __shared__ float red[256];
    red[tid] = ss;
    __syncthreads();
    for (int s = 128; s > 0; s >>= 1) {
        if (tid < s) red[tid] += red[tid + s];
        __syncthreads();
    }
    float rms = rsqrtf(red[0] / (float)HIDDEN + 1e-6f);
    if (vld) {
        for (int i = tid; i < HIDDEN / 4; i += blockDim.x) {
            float4 v = x[i], ww = w[i];
            out[i] = make_float4(v.x * rms * (ww.x + 1.f),
                                 v.y * rms * (ww.y + 1.f),
                                 v.z * rms * (ww.z + 1.f),
                                 v.w * rms * (ww.w + 1.f));
        }
    } else {
        float4 z = make_float4(0.f, 0.f, 0.f, 0.f);
        for (int i = tid; i < HIDDEN / 4; i += blockDim.x) out[i] = z;
    }
}

// ---------------------------------------------------------------------------
// 3xTF32 tensor-core GEMM template (FP32-emulation precision).
// C[m,n] = sum_k A[m,k] * B[n,k]   (both row-major with K contiguous)
// Each operand split x = hi + lo (tf32 each); acc += aH*bH + aH*bL + aL*bH.
// Tile 128x128x8, 256 threads, 8 warps (2 warp-rows x 4 warp-cols),
// each warp 64x32 via 4x4 m16n8k8 fragments, 3 mmas per fragment pair.
// MODE 0: QKV   A=g_hnorm          B=qkv_w[mod]    C=g_qkv    (N=7208 guard)
// MODE 1: S     A=g_q[head z]      B=g_k[head z]   C=g_s
// MODE 2: O=PV  A=g_s              B=g_vt[head z]  C=g_o (gated epilogue)
// MODE 3: PROJ  A=g_o              B=proj_w[mod]   C=d_out (scatter rows)
// ---------------------------------------------------------------------------
__device__ __forceinline__ void split_tf32(float x, unsigned& hi, unsigned& lo) {
    unsigned h;
    asm("cvt.rna.tf32.f32 %0, %1;" : "=r"(h) : "f"(x));
    float hf = __uint_as_float(h);
    unsigned l;
    asm("cvt.rna.tf32.f32 %0, %1;" : "=r"(l) : "f"(x - hf));
    hi = h; lo = l;
}
__device__ __forceinline__ void mma8(float* c, unsigned a0, unsigned a1,
                                     unsigned a2, unsigned a3,
                                     unsigned b0, unsigned b1) {
    asm volatile(
        "mma.sync.aligned.m16n8k8.row.col.f32.tf32.tf32.f32 "
        "{%0,%1,%2,%3}, {%4,%5,%6,%7}, {%8,%9}, {%0,%1,%2,%3};"
        : "+f"(c[0]), "+f"(c[1]), "+f"(c[2]), "+f"(c[3])
        : "r"(a0), "r"(a1), "r"(a2), "r"(a3), "r"(b0), "r"(b1));
}

template <int MODE>
__global__ __launch_bounds__(256) void gemm_k(const float* __restrict__ Bw,
                                              float* __restrict__ Cout,
                                              int z) {
    constexpr int KD   = (MODE == 0) ? HIDDEN : (MODE == 1) ? HEAD_DIM
                       : (MODE == 2) ? NPAD   : Q_SIZE;
    constexpr int NACT = (MODE == 0) ? QKV_OUT : (MODE == 1) ? NPAD
                       : (MODE == 2) ? HEAD_DIM : HIDDEN;
    constexpr int NK = KD / 8;

    __shared__ unsigned Ast[2][8][136];   // [hi/lo][k][m], 136-pad: conflict-free frags
    __shared__ unsigned Bst[2][8][136];

    const int tid   = threadIdx.x;
    const int tileN = blockIdx.x * 128;
    const int tileM = blockIdx.y * 128;

    const float* A;
    const float* B;
    if constexpr (MODE == 0) {
        A = g_hnorm;
        B = Bw + (size_t)g_rowMod[tileM] * ((size_t)QKV_OUT * HIDDEN);
    } else if constexpr (MODE == 1) {
        A = g_q + (size_t)z * 5 * NPAD * HEAD_DIM;
        B = g_k + (size_t)z * NPAD * HEAD_DIM;
    } else if constexpr (MODE == 2) {
        A = g_s;
        B = g_vt + (size_t)z * HEAD_DIM * NPAD;
    } else {
        A = g_o;
        B = Bw + (size_t)g_rowMod[tileM] * ((size_t)HIDDEN * Q_SIZE);
    }

    const int rowL = tid >> 1;           // 0..127
    const int cg   = tid & 1;            // k-half (4 floats each)
    const int lane = tid & 31, warp = tid >> 5;
    const int gid = lane >> 2, tig = lane & 3;
    const int wm = (warp & 1) * 64, wn = (warp >> 1) * 32;

    float acc[4][4][4];
#pragma unroll
    for (int i = 0; i < 4; i++)
#pragma unroll
        for (int j = 0; j < 4; j++)
#pragma unroll
            for (int e = 0; e < 4; e++) acc[i][j][e] = 0.f;

    float4 av, bv;
    const float4 zero4 = make_float4(0.f, 0.f, 0.f, 0.f);

#define LOAD_STAGE(kt)                                                          \
    do {                                                                        \
        int k0 = (kt)*8 + cg * 4;                                               \
        av = *reinterpret_cast<const float4*>(A + (size_t)(tileM + rowL) * KD + k0); \
        int n0 = tileN + rowL;                                                  \
        bv = (n0 < NACT)                                                        \
                 ? *reinterpret_cast<const float4*>(B + (size_t)n0 * KD + k0)   \
                 : zero4;                                                       \
    } while (0)

#define STORE_STAGE()                                                           \
    do {                                                                        \
        unsigned h, l;                                                          \
        split_tf32(av.x, h, l); Ast[0][cg*4+0][rowL] = h; Ast[1][cg*4+0][rowL] = l; \
        split_tf32(av.y, h, l); Ast[0][cg*4+1][rowL] = h; Ast[1][cg*4+1][rowL] = l; \
        split_tf32(av.z, h, l); Ast[0][cg*4+2][rowL] = h; Ast[1][cg*4+2][rowL] = l; \
        split_tf32(av.w, h, l); Ast[0][cg*4+3][rowL] = h; Ast[1][cg*4+3][rowL] = l; \
        split_tf32(bv.x, h, l); Bst[0][cg*4+0][rowL] = h; Bst[1][cg*4+0][rowL] = l; \
        split_tf32(bv.y, h, l); Bst[0][cg*4+1][rowL] = h; Bst[1][cg*4+1][rowL] = l; \
        split_tf32(bv.z, h, l); Bst[0][cg*4+2][rowL] = h; Bst[1][cg*4+2][rowL] = l; \
        split_tf32(bv.w, h, l); Bst[0][cg*4+3][rowL] = h; Bst[1][cg*4+3][rowL] = l; \
    } while (0)

    LOAD_STAGE(0);
    for (int kt = 0; kt < NK; kt++) {
        __syncthreads();
        STORE_STAGE();
        __syncthreads();
        if (kt + 1 < NK) LOAD_STAGE(kt + 1);

        unsigned aH[4][4], aL[4][4], bH[4][2], bL[4][2];
#pragma unroll
        for (int mi = 0; mi < 4; mi++) {
            int m0 = wm + mi * 16 + gid;
            aH[mi][0] = Ast[0][tig][m0];     aL[mi][0] = Ast[1][tig][m0];
            aH[mi][1] = Ast[0][tig][m0 + 8]; aL[mi][1] = Ast[1][tig][m0 + 8];
            aH[mi][2] = Ast[0][tig + 4][m0]; aL[mi][2] = Ast[1][tig + 4][m0];
            aH[mi][3] = Ast[0][tig + 4][m0 + 8]; aL[mi][3] = Ast[1][tig + 4][m0 + 8];
        }
#pragma unroll
        for (int ni = 0; ni < 4; ni++) {
            int n0 = wn + ni * 8 + gid;
            bH[ni][0] = Bst[0][tig][n0];     bL[ni][0] = Bst[1][tig][n0];
            bH[ni][1] = Bst[0][tig + 4][n0]; bL[ni][1] = Bst[1][tig + 4][n0];
        }
#pragma unroll
        for (int mi = 0; mi < 4; mi++)
#pragma unroll
            for (int ni = 0; ni < 4; ni++) {
                mma8(acc[mi][ni], aH[mi][0], aH[mi][1], aH[mi][2], aH[mi][3],
                     bH[ni][0], bH[ni][1]);
                mma8(acc[mi][ni], aH[mi][0], aH[mi][1], aH[mi][2], aH[mi][3],
                     bL[ni][0], bL[ni][1]);
                mma8(acc[mi][ni], aL[mi][0], aL[mi][1], aL[mi][2], aL[mi][3],
                     bH[ni][0], bH[ni][1]);
            }
    }
#undef LOAD_STAGE
#undef STORE_STAGE

    // Epilogue: c0/c1 -> (r0, c0..c0+1), c2/c3 -> (r0+8, same cols)
#pragma unroll
    for (int mi = 0; mi < 4; mi++) {
#pragma unroll
        for (int ni = 0; ni < 4; ni++) {
            int r0 = tileM + wm + mi * 16 + gid;
            int c0 = tileN + wn + ni * 8 + tig * 2;
            float* cc = acc[mi][ni];
            if constexpr (MODE == 0) {
                if (c0 < QKV_OUT) {
                    *(float2*)&g_qkv[(size_t)r0 * QKV_OUT + c0] =
                        make_float2(cc[0], cc[1]);
                    *(float2*)&g_qkv[(size_t)(r0 + 8) * QKV_OUT + c0] =
                        make_float2(cc[2], cc[3]);
                }
            } else if constexpr (MODE == 1) {
                *(float2*)&g_s[(size_t)r0 * NPAD + c0] =
                    make_float2(cc[0], cc[1]);
                *(float2*)&g_s[(size_t)(r0 + 8) * NPAD + c0] =
                    make_float2(cc[2], cc[3]);
            } else if constexpr (MODE == 2) {
#pragma unroll
                for (int e = 0; e < 4; e++) {
                    int r   = r0 + ((e >= 2) ? 8 : 0);
                    int col = c0 + (e & 1);
                    int gq  = r / NPAD;
                    int rr  = r - gq * NPAD;
                    int hq  = z * 5 + gq;
                    float gv  = g_gate[rr * HQ + hq];
                    float sig = 1.f / (1.f + __expf(-gv));
                    g_o[(size_t)rr * Q_SIZE + hq * HEAD_DIM + col] = cc[e] * sig;
                }
            } else {
                if (g_valid[r0])
                    *(float2*)&Cout[(size_t)g_srcTok[r0] * HIDDEN + c0] =
                        make_float2(cc[0], cc[1]);
                if (g_valid[r0 + 8])
                    *(float2*)&Cout[(size_t)g_srcTok[r0 + 8] * HIDDEN + c0] =
                        make_float2(cc[2], cc[3]);
            }
        }
    }
}

// ---------------------------------------------------------------------------
// QKV post-processing: per-head RMSNorm (q,k) + RoPE + q-scale,
// V transpose into [kv][d][r], gate stash. One block per sorted row.
// ---------------------------------------------------------------------------
__global__ void k_qkvpost(const float* __restrict__ rope,
                          const float* __restrict__ qnw,
                          const float* __restrict__ knw) {
    int r = blockIdx.x, tid = threadIdx.x;
    int src = g_srcTok[r];
    int mod = g_rowMod[r];
    __shared__ float sn[64], sc[64];
    if (tid < 64)       sn[tid]      = rope[(size_t)src * HEAD_DIM + tid];
    else if (tid < 128) sc[tid - 64] = rope[(size_t)src * HEAD_DIM + tid];
    const float* row = g_qkv + (size_t)r * QKV_OUT;
    __syncthreads();

    int lane = tid & 31, warp = tid >> 5;
    for (int hh = warp; hh < HQ + HKV; hh += 8) {
        const float* xp;
        const float* wp;
        if (hh < HQ) { xp = row + hh * HEAD_DIM;                 wp = qnw + mod * HEAD_DIM; }
        else         { xp = row + Q_SIZE + (hh - HQ) * HEAD_DIM; wp = knw + mod * HEAD_DIM; }
        float x0 = xp[lane], x1 = xp[lane + 32], x2 = xp[lane + 64], x3 = xp[lane + 96];
        float ssq = x0 * x0 + x1 * x1 + x2 * x2 + x3 * x3;
#pragma unroll
        for (int o = 16; o > 0; o >>= 1) ssq += __shfl_xor_sync(0xffffffffu, ssq, o);
        float rms = rsqrtf(ssq / (float)HEAD_DIM + 1e-6f);
        float y0 = x0 * rms * (wp[lane] + 1.f);
        float y1 = x1 * rms * (wp[lane + 32] + 1.f);
        float y2 = x2 * rms * (wp[lane + 64] + 1.f);
        float y3 = x3 * rms * (wp[lane + 96] + 1.f);
        float c0 = sc[lane], s0 = sn[lane];
        float c1 = sc[lane + 32], s1 = sn[lane + 32];
        float o0 = y0 * c0 - y2 * s0;
        float o2 = y0 * s0 + y2 * c0;
        float o1 = y1 * c1 - y3 * s1;
        float o3 = y1 * s1 + y3 * c1;
        if (hh < HQ) {
            const float scl = 0.08838834764831845f;  // 1/sqrt(128), folded into q
            float* q = g_q + ((size_t)hh * NPAD + r) * HEAD_DIM;
            q[lane] = o0 * scl; q[lane + 32] = o1 * scl;
            q[lane + 64] = o2 * scl; q[lane + 96] = o3 * scl;
        } else {
            float* k = g_k + ((size_t)(hh - HQ) * NPAD + r) * HEAD_DIM;
            k[lane] = o0; k[lane + 32] = o1; k[lane + 64] = o2; k[lane + 96] = o3;
        }
    }
    // V transpose: g_vt[kv][d][r] = v[r][kv][d]
    for (int idx = tid; idx < HKV * HEAD_DIM; idx += blockDim.x) {
        int kh = idx >> 7, d = idx & 127;
        g_vt[((size_t)kh * HEAD_DIM + d) * NPAD + r] = row[Q_SIZE + KV_SIZE + idx];
    }
    if (tid < HQ) g_gate[r * HQ + tid] = row[Q_SIZE + 2 * KV_SIZE + tid];
}

// ---------------------------------------------------------------------------
// Masked softmax over key dim (width NPAD = 2304 = 9*256); P overwrites S.
// Invalid (pad) keys -> probability 0.
// ---------------------------------------------------------------------------
__global__ void k_softmax() {
    int tid  = threadIdx.x;
    float* p = g_s + (size_t)blockIdx.x * NPAD;
    float loc[9];
    float mx = -1e30f;
#pragma unroll
    for (int j = 0; j < 9; j++) {
        int c = tid + j * 256;
        float v = g_valid[c] ? p[c] : -1e30f;
        loc[j] = v;
        mx = fmaxf(mx, v);
    }
    __shared__ float red[256];
    red[tid] = mx;
    __syncthreads();
    for (int s = 128; s > 0; s >>= 1) {
        if (tid < s) red[tid] = fmaxf(red[tid], red[tid + s]);
        __syncthreads();
    }
    float m = red[0];
    __syncthreads();
    float sum = 0.f;
#pragma unroll
    for (int j = 0; j < 9; j++) {
        float e = (loc[j] > -1e29f) ? __expf(loc[j] - m) : 0.f;
        loc[j] = e;
        sum += e;
    }
    red[tid] = sum;
    __syncthreads();
    for (int s = 128; s > 0; s >>= 1) {
        if (tid < s) red[tid] += red[tid + s];
        __syncthreads();
    }
    float inv = 1.f / red[0];
#pragma unroll
    for (int j = 0; j < 9; j++) p[tid + j * 256] = loc[j] * inv;
}

// ---------------------------------------------------------------------------
// Launcher (graph-capturable: kernel launches only)
// ---------------------------------------------------------------------------
extern "C" void kernel_launch(void* const* d_in, const int* in_sizes, int n_in,
                              void* d_out, int out_size) {
    const float* hidden     = (const float*)d_in[0];
    const float* rope       = (const float*)d_in[1];
    const float* pre_norm_w = (const float*)d_in[2];
    const float* qkv_w      = (const float*)d_in[3];
    const float* q_norm_w   = (const float*)d_in[4];
    const float* k_norm_w   = (const float*)d_in[5];
    const float* proj_w     = (const float*)d_in[6];
    const int*   midsRaw    = (const int*)d_in[7];   // int32 OR int64, detected
    float*       out        = (float*)d_out;

    k_meta1<<<1, 256>>>(midsRaw);
    k_meta2<<<8, 256>>>(midsRaw);
    k_norm<<<NPAD, 256>>>(hidden, pre_norm_w);
    // QKV: C[2304, 7208] (N tiles = ceil(7208/128)=57)
    gemm_k<0><<<dim3(57, NPAD / 128, 1), 256>>>(qkv_w, nullptr, 0);
    k_qkvpost<<<NPAD, 256>>>(rope, q_norm_w, k_norm_w);
    // Attention per kv head, reusing g_s (106 MB) sequentially
    for (int h = 0; h < HKV; h++) {
        // S = Q K^T: [11520, 2304]
        gemm_k<1><<<dim3(NPAD / 128, MROWS / 128, 1), 256>>>(nullptr, nullptr, h);
        k_softmax<<<MROWS, 256>>>();
        // O = P V: [11520, 128] (gated epilogue -> g_o)
        gemm_k<2><<<dim3(1, MROWS / 128, 1), 256>>>(nullptr, nullptr, h);
    }
    // Projection + scatter to original token order
    gemm_k<3><<<dim3(HIDDEN / 128, NPAD / 128, 1), 256>>>(proj_w, out, 0);
}

// round 6
// speedup vs baseline: 1.1542x; 1.1542x over previous
#include <cuda_runtime.h>
#include <cuda_bf16.h>
#include <math.h>

// ---------------------------------------------------------------------------
// Problem constants
// ---------------------------------------------------------------------------
#define N_TOKS   2048
#define HIDDEN   5120
#define HEAD_DIM 128
#define HQ       40
#define HKV      8
#define NUM_MOD  3
#define Q_SIZE   5120           // HQ * HEAD_DIM
#define KV_SIZE  1024           // HKV * HEAD_DIM
#define GATE_N   40
#define QKV_OUT  7208           // Q_SIZE + 2*KV_SIZE + GATE_N
#define NPAD     2304           // max padded sorted rows (segments 128-aligned)
#define MROWS    (5 * NPAD)     // q-rows per kv head (group size 5) = 11520
#define HCHUNK   4              // kv heads processed per attention pass

// ---------------------------------------------------------------------------
// Scratch (static device globals; total ~760 MB)
// ---------------------------------------------------------------------------
__device__ float g_hnorm[(size_t)NPAD * HIDDEN];           // 47 MB
__device__ float g_qkv[(size_t)NPAD * QKV_OUT];            // 66 MB
__device__ float g_q[(size_t)HQ * NPAD * HEAD_DIM];        // 47 MB  [hq][r][d], hq = kv*5+g
__device__ float g_k[(size_t)HKV * NPAD * HEAD_DIM];       // 9.4 MB [kv][r][d]
__device__ float g_vt[(size_t)HKV * HEAD_DIM * NPAD];      // 9.4 MB [kv][d][r]  (transposed)
__device__ float g_s[(size_t)HCHUNK * MROWS * NPAD];       // 425 MB, 4 heads per pass
__device__ float g_o[(size_t)NPAD * Q_SIZE];               // 47 MB
__device__ float g_gate[NPAD * HQ];
__device__ int   g_rowMod[NPAD];
__device__ int   g_valid[NPAD];
__device__ int   g_srcTok[NPAD];
__device__ int   g_segStart[NUM_MOD + 1];
__device__ int   g_is64;

// Dtype-robust modality read (mids may be int32 or int64; detected at runtime).
__device__ __forceinline__ int getMid(const int* raw, int i, int is64) {
    return is64 ? (int)(reinterpret_cast<const long long*>(raw)[i]) : raw[i];
}

// ---------------------------------------------------------------------------
// Metadata kernels: deterministic modality sort (segments 128-aligned)
// ---------------------------------------------------------------------------
__global__ void k_meta1(const int* __restrict__ midsRaw) {
    __shared__ int cnt[NUM_MOD];
    __shared__ int sstart[NUM_MOD + 1];
    __shared__ int oddNZ;
    int tid = threadIdx.x;
    if (tid == 0) oddNZ = 0;
    if (tid < NUM_MOD) cnt[tid] = 0;
    __syncthreads();
    // int64 data has zero high-words at odd int32 positions; int32 data doesn't.
    for (int i = tid; i < N_TOKS / 2; i += blockDim.x)
        if (midsRaw[2 * i + 1] != 0) atomicExch(&oddNZ, 1);
    __syncthreads();
    int is64 = (oddNZ == 0);
    if (tid == 0) g_is64 = is64;

    for (int i = tid; i < N_TOKS; i += blockDim.x)
        atomicAdd(&cnt[getMid(midsRaw, i, is64)], 1);
    __syncthreads();
    if (tid == 0) {
        int s = 0;
        for (int m = 0; m < NUM_MOD; m++) {
            sstart[m] = s;
            g_segStart[m] = s;
            s += (cnt[m] + 127) & ~127;
        }
        sstart[NUM_MOD] = s;
        g_segStart[NUM_MOD] = s;
    }
    __syncthreads();
    for (int r = tid; r < NPAD; r += blockDim.x) {
        int mod = 0;
        if (r >= sstart[1]) mod = 1;
        if (r >= sstart[2]) mod = 2;
        if (r >= sstart[3]) mod = 0;   // tail beyond actual padded length
        g_rowMod[r] = mod;
        g_valid[r]  = 0;
        g_srcTok[r] = 0;
    }
}

// Deterministic rank: token i's slot = segStart[m] + #{j<i : mid[j]==m}
__global__ void k_meta2(const int* __restrict__ midsRaw) {
    int i = blockIdx.x * blockDim.x + threadIdx.x;
    if (i >= N_TOKS) return;
    int is64 = g_is64;
    int m = getMid(midsRaw, i, is64);
    int rank = 0;
    for (int j = 0; j < i; j++) rank += (getMid(midsRaw, j, is64) == m);
    int pos = g_segStart[m] + rank;
    g_srcTok[pos] = i;
    g_valid[pos]  = 1;
}

// ---------------------------------------------------------------------------
// Pre-norm RMSNorm + gather into sorted order (pads -> zeros)
// ---------------------------------------------------------------------------
__global__ void k_norm(const float* __restrict__ hidden,
                       const float* __restrict__ pnw) {
    int r = blockIdx.x, tid = threadIdx.x;
    int vld = g_valid[r];
    int src = g_srcTok[r];
    int mod = g_rowMod[r];
    const float4* x   = reinterpret_cast<const float4*>(hidden + (size_t)src * HIDDEN);
    const float4* w   = reinterpret_cast<const float4*>(pnw + mod * HIDDEN);
    float4*       out = reinterpret_cast<float4*>(g_hnorm + (size_t)r * HIDDEN);

    float ss = 0.f;
    if (vld) {
        for (int i = tid; i < HIDDEN / 4; i += blockDim.x) {
            float4 v = x[i];
            ss += v.x * v.x + v.y * v.y + v.z * v.z + v.w * v.w;
        }
    }
    __shared__ float red[256];
    red[tid] = ss;
    __syncthreads();
    for (int s = 128; s > 0; s >>= 1) {
        if (tid < s) red[tid] += red[tid + s];
        __syncthreads();
    }
    float rms = rsqrtf(red[0] / (float)HIDDEN + 1e-6f);
    if (vld) {
        for (int i = tid; i < HIDDEN / 4; i += blockDim.x) {
            float4 v = x[i], ww = w[i];
            out[i] = make_float4(v.x * rms * (ww.x + 1.f),
                                 v.y * rms * (ww.y + 1.f),
                                 v.z * rms * (ww.z + 1.f),
                                 v.w * rms * (ww.w + 1.f));
        }
    } else {
        float4 z = make_float4(0.f, 0.f, 0.f, 0.f);
        for (int i = tid; i < HIDDEN / 4; i += blockDim.x) out[i] = z;
    }
}

// ---------------------------------------------------------------------------
// 3xTF32 tensor-core GEMM, double-buffered smem pipeline.
// C[m,n] = sum_k A[m,k] * B[n,k]   (both row-major with K contiguous)
// Each operand split x = hi + lo (tf32 each); acc += aH*bH + aH*bL + aL*bH.
// Tile 128x128x8, 256 threads, 8 warps (2 warp-rows x 4 warp-cols),
// each warp 64x32 via 4x4 m16n8k8 fragments, 3 mmas per fragment pair.
// One __syncthreads per k-slab; next slab's LDG overlaps current MMAs.
// MODE 0: QKV   A=g_hnorm          B=qkv_w[mod]    C=g_qkv    (N=7208 guard)
// MODE 1: S     A=g_q[head]        B=g_k[head]     C=g_s[chunk slot]
// MODE 2: O=PV  A=g_s[chunk slot]  B=g_vt[head]    C=g_o (gated epilogue)
// MODE 3: PROJ  A=g_o              B=proj_w[mod]   C=d_out (scatter rows)
// Modes 1/2: head = z + blockIdx.z, chunk slot = blockIdx.z.
// ---------------------------------------------------------------------------
__device__ __forceinline__ void split_tf32(float x, unsigned& hi, unsigned& lo) {
    unsigned h;
    asm("cvt.rna.tf32.f32 %0, %1;" : "=r"(h) : "f"(x));
    float hf = __uint_as_float(h);
    unsigned l;
    asm("cvt.rna.tf32.f32 %0, %1;" : "=r"(l) : "f"(x - hf));
    hi = h; lo = l;
}
__device__ __forceinline__ void mma8(float* c, unsigned a0, unsigned a1,
                                     unsigned a2, unsigned a3,
                                     unsigned b0, unsigned b1) {
    asm volatile(
        "mma.sync.aligned.m16n8k8.row.col.f32.tf32.tf32.f32 "
        "{%0,%1,%2,%3}, {%4,%5,%6,%7}, {%8,%9}, {%0,%1,%2,%3};"
        : "+f"(c[0]), "+f"(c[1]), "+f"(c[2]), "+f"(c[3])
        : "r"(a0), "r"(a1), "r"(a2), "r"(a3), "r"(b0), "r"(b1));
}

template <int MODE>
__global__ __launch_bounds__(256) void gemm_k(const float* __restrict__ Bw,
                                              float* __restrict__ Cout,
                                              int z) {
    constexpr int KD   = (MODE == 0) ? HIDDEN : (MODE == 1) ? HEAD_DIM
                       : (MODE == 2) ? NPAD   : Q_SIZE;
    constexpr int NACT = (MODE == 0) ? QKV_OUT : (MODE == 1) ? NPAD
                       : (MODE == 2) ? HEAD_DIM : HIDDEN;
    constexpr int NK = KD / 8;

    __shared__ unsigned Ast[2][2][8][136];   // [stage][hi/lo][k][m]; 34.8 KB total
    __shared__ unsigned Bst[2][2][8][136];

    const int tid   = threadIdx.x;
    const int tileN = blockIdx.x * 128;
    const int tileM = blockIdx.y * 128;
    const int zz    = z + blockIdx.z;                        // head (modes 1/2)
    const size_t sbase = (size_t)blockIdx.z * MROWS * NPAD;  // g_s slot (modes 1/2)

    const float* A;
    const float* B;
    if constexpr (MODE == 0) {
        A = g_hnorm;
        B = Bw + (size_t)g_rowMod[tileM] * ((size_t)QKV_OUT * HIDDEN);
    } else if constexpr (MODE == 1) {
        A = g_q + (size_t)zz * 5 * NPAD * HEAD_DIM;
        B = g_k + (size_t)zz * NPAD * HEAD_DIM;
    } else if constexpr (MODE == 2) {
        A = g_s + sbase;
        B = g_vt + (size_t)zz * HEAD_DIM * NPAD;
    } else {
        A = g_o;
        B = Bw + (size_t)g_rowMod[tileM] * ((size_t)HIDDEN * Q_SIZE);
    }

    const int rowL = tid >> 1;           // 0..127
    const int cg   = tid & 1;            // k-half (4 floats each)
    const int lane = tid & 31, warp = tid >> 5;
    const int gid = lane >> 2, tig = lane & 3;
    const int wm = (warp & 1) * 64, wn = (warp >> 1) * 32;

    float acc[4][4][4];
#pragma unroll
    for (int i = 0; i < 4; i++)
#pragma unroll
        for (int j = 0; j < 4; j++)
#pragma unroll
            for (int e = 0; e < 4; e++) acc[i][j][e] = 0.f;

    float4 av, bv;
    const float4 zero4 = make_float4(0.f, 0.f, 0.f, 0.f);

#define LOAD_STAGE(kt)                                                          \
    do {                                                                        \
        int k0 = (kt)*8 + cg * 4;                                               \
        av = *reinterpret_cast<const float4*>(A + (size_t)(tileM + rowL) * KD + k0); \
        int n0 = tileN + rowL;                                                  \
        bv = (n0 < NACT)                                                        \
                 ? *reinterpret_cast<const float4*>(B + (size_t)n0 * KD + k0)   \
                 : zero4;                                                       \
    } while (0)

#define STORE_STAGE(st)                                                         \
    do {                                                                        \
        unsigned h, l;                                                          \
        split_tf32(av.x, h, l); Ast[st][0][cg*4+0][rowL] = h; Ast[st][1][cg*4+0][rowL] = l; \
        split_tf32(av.y, h, l); Ast[st][0][cg*4+1][rowL] = h; Ast[st][1][cg*4+1][rowL] = l; \
        split_tf32(av.z, h, l); Ast[st][0][cg*4+2][rowL] = h; Ast[st][1][cg*4+2][rowL] = l; \
        split_tf32(av.w, h, l); Ast[st][0][cg*4+3][rowL] = h; Ast[st][1][cg*4+3][rowL] = l; \
        split_tf32(bv.x, h, l); Bst[st][0][cg*4+0][rowL] = h; Bst[st][1][cg*4+0][rowL] = l; \
        split_tf32(bv.y, h, l); Bst[st][0][cg*4+1][rowL] = h; Bst[st][1][cg*4+1][rowL] = l; \
        split_tf32(bv.z, h, l); Bst[st][0][cg*4+2][rowL] = h; Bst[st][1][cg*4+2][rowL] = l; \
        split_tf32(bv.w, h, l); Bst[st][0][cg*4+3][rowL] = h; Bst[st][1][cg*4+3][rowL] = l; \
    } while (0)

    LOAD_STAGE(0);
    STORE_STAGE(0);
    __syncthreads();
    for (int kt = 0; kt < NK; kt++) {
        const int cur = kt & 1;
        const bool more = (kt + 1 < NK);
        if (more) LOAD_STAGE(kt + 1);   // LDG latency hidden under the MMAs below

        unsigned aH[4][4], aL[4][4], bH[4][2], bL[4][2];
#pragma unroll
        for (int mi = 0; mi < 4; mi++) {
            int m0 = wm + mi * 16 + gid;
            aH[mi][0] = Ast[cur][0][tig][m0];     aL[mi][0] = Ast[cur][1][tig][m0];
            aH[mi][1] = Ast[cur][0][tig][m0 + 8]; aL[mi][1] = Ast[cur][1][tig][m0 + 8];
            aH[mi][2] = Ast[cur][0][tig + 4][m0]; aL[mi][2] = Ast[cur][1][tig + 4][m0];
            aH[mi][3] = Ast[cur][0][tig + 4][m0 + 8]; aL[mi][3] = Ast[cur][1][tig + 4][m0 + 8];
        }
#pragma unroll
        for (int ni = 0; ni < 4; ni++) {
            int n0 = wn + ni * 8 + gid;
            bH[ni][0] = Bst[cur][0][tig][n0];     bL[ni][0] = Bst[cur][1][tig][n0];
            bH[ni][1] = Bst[cur][0][tig + 4][n0]; bL[ni][1] = Bst[cur][1][tig + 4][n0];
        }
#pragma unroll
        for (int mi = 0; mi < 4; mi++)
#pragma unroll
            for (int ni = 0; ni < 4; ni++) {
                mma8(acc[mi][ni], aH[mi][0], aH[mi][1], aH[mi][2], aH[mi][3],
                     bH[ni][0], bH[ni][1]);
                mma8(acc[mi][ni], aH[mi][0], aH[mi][1], aH[mi][2], aH[mi][3],
                     bL[ni][0], bL[ni][1]);
                mma8(acc[mi][ni], aL[mi][0], aL[mi][1], aL[mi][2], aL[mi][3],
                     bH[ni][0], bH[ni][1]);
            }
        if (more) STORE_STAGE(cur ^ 1);
        __syncthreads();
    }
#undef LOAD_STAGE
#undef STORE_STAGE

    // Epilogue: c0/c1 -> (r0, c0..c0+1), c2/c3 -> (r0+8, same cols)
#pragma unroll
    for (int mi = 0; mi < 4; mi++) {
#pragma unroll
        for (int ni = 0; ni < 4; ni++) {
            int r0 = tileM + wm + mi * 16 + gid;
            int c0 = tileN + wn + ni * 8 + tig * 2;
            float* cc = acc[mi][ni];
            if constexpr (MODE == 0) {
                if (c0 < QKV_OUT) {
                    *(float2*)&g_qkv[(size_t)r0 * QKV_OUT + c0] =
                        make_float2(cc[0], cc[1]);
                    *(float2*)&g_qkv[(size_t)(r0 + 8) * QKV_OUT + c0] =
                        make_float2(cc[2], cc[3]);
                }
            } else if constexpr (MODE == 1) {
                *(float2*)&g_s[sbase + (size_t)r0 * NPAD + c0] =
                    make_float2(cc[0], cc[1]);
                *(float2*)&g_s[sbase + (size_t)(r0 + 8) * NPAD + c0] =
                    make_float2(cc[2], cc[3]);
            } else if constexpr (MODE == 2) {
#pragma unroll
                for (int e = 0; e < 4; e++) {
                    int r   = r0 + ((e >= 2) ? 8 : 0);
                    int col = c0 + (e & 1);
                    int gq  = r / NPAD;
                    int rr  = r - gq * NPAD;
                    int hq  = zz * 5 + gq;
                    float gv  = g_gate[rr * HQ + hq];
                    float sig = 1.f / (1.f + __expf(-gv));
                    g_o[(size_t)rr * Q_SIZE + hq * HEAD_DIM + col] = cc[e] * sig;
                }
            } else {
                if (g_valid[r0])
                    *(float2*)&Cout[(size_t)g_srcTok[r0] * HIDDEN + c0] =
                        make_float2(cc[0], cc[1]);
                if (g_valid[r0 + 8])
                    *(float2*)&Cout[(size_t)g_srcTok[r0 + 8] * HIDDEN + c0] =
                        make_float2(cc[2], cc[3]);
            }
        }
    }
}

// ---------------------------------------------------------------------------
// QKV post-processing: per-head RMSNorm (q,k) + RoPE + q-scale,
// V transpose into [kv][d][r], gate stash. One block per sorted row.
// ---------------------------------------------------------------------------
__global__ void k_qkvpost(const float* __restrict__ rope,
                          const float* __restrict__ qnw,
                          const float* __restrict__ knw) {
    int r = blockIdx.x, tid = threadIdx.x;
    int src = g_srcTok[r];
    int mod = g_rowMod[r];
    __shared__ float sn[64], sc[64];
    if (tid < 64)       sn[tid]      = rope[(size_t)src * HEAD_DIM + tid];
    else if (tid < 128) sc[tid - 64] = rope[(size_t)src * HEAD_DIM + tid];
    const float* row = g_qkv + (size_t)r * QKV_OUT;
    __syncthreads();

    int lane = tid & 31, warp = tid >> 5;
    for (int hh = warp; hh < HQ + HKV; hh += 8) {
        const float* xp;
        const float* wp;
        if (hh < HQ) { xp = row + hh * HEAD_DIM;                 wp = qnw + mod * HEAD_DIM; }
        else         { xp = row + Q_SIZE + (hh - HQ) * HEAD_DIM; wp = knw + mod * HEAD_DIM; }
        float x0 = xp[lane], x1 = xp[lane + 32], x2 = xp[lane + 64], x3 = xp[lane + 96];
        float ssq = x0 * x0 + x1 * x1 + x2 * x2 + x3 * x3;
#pragma unroll
        for (int o = 16; o > 0; o >>= 1) ssq += __shfl_xor_sync(0xffffffffu, ssq, o);
        float rms = rsqrtf(ssq / (float)HEAD_DIM + 1e-6f);
        float y0 = x0 * rms * (wp[lane] + 1.f);
        float y1 = x1 * rms * (wp[lane + 32] + 1.f);
        float y2 = x2 * rms * (wp[lane + 64] + 1.f);
        float y3 = x3 * rms * (wp[lane + 96] + 1.f);
        float c0 = sc[lane], s0 = sn[lane];
        float c1 = sc[lane + 32], s1 = sn[lane + 32];
        float o0 = y0 * c0 - y2 * s0;
        float o2 = y0 * s0 + y2 * c0;
        float o1 = y1 * c1 - y3 * s1;
        float o3 = y1 * s1 + y3 * c1;
        if (hh < HQ) {
            const float scl = 0.08838834764831845f;  // 1/sqrt(128), folded into q
            float* q = g_q + ((size_t)hh * NPAD + r) * HEAD_DIM;
            q[lane] = o0 * scl; q[lane + 32] = o1 * scl;
            q[lane + 64] = o2 * scl; q[lane + 96] = o3 * scl;
        } else {
            float* k = g_k + ((size_t)(hh - HQ) * NPAD + r) * HEAD_DIM;
            k[lane] = o0; k[lane + 32] = o1; k[lane + 64] = o2; k[lane + 96] = o3;
        }
    }
    // V transpose: g_vt[kv][d][r] = v[r][kv][d]
    for (int idx = tid; idx < HKV * HEAD_DIM; idx += blockDim.x) {
        int kh = idx >> 7, d = idx & 127;
        g_vt[((size_t)kh * HEAD_DIM + d) * NPAD + r] = row[Q_SIZE + KV_SIZE + idx];
    }
    if (tid < HQ) g_gate[r * HQ + tid] = row[Q_SIZE + 2 * KV_SIZE + tid];
}

// ---------------------------------------------------------------------------
// Masked softmax over key dim (width NPAD = 2304 = 9*256); P overwrites S.
// Grid covers HCHUNK * MROWS rows of the 4-head g_s buffer.
// ---------------------------------------------------------------------------
__global__ void k_softmax() {
    int tid  = threadIdx.x;
    float* p = g_s + (size_t)blockIdx.x * NPAD;
    float loc[9];
    float mx = -1e30f;
#pragma unroll
    for (int j = 0; j < 9; j++) {
        int c = tid + j * 256;
        float v = g_valid[c] ? p[c] : -1e30f;
        loc[j] = v;
        mx = fmaxf(mx, v);
    }
    __shared__ float red[256];
    red[tid] = mx;
    __syncthreads();
    for (int s = 128; s > 0; s >>= 1) {
        if (tid < s) red[tid] = fmaxf(red[tid], red[tid + s]);
        __syncthreads();
    }
    float m = red[0];
    __syncthreads();
    float sum = 0.f;
#pragma unroll
    for (int j = 0; j < 9; j++) {
        float e = (loc[j] > -1e29f) ? __expf(loc[j] - m) : 0.f;
        loc[j] = e;
        sum += e;
    }
    red[tid] = sum;
    __syncthreads();
    for (int s = 128; s > 0; s >>= 1) {
        if (tid < s) red[tid] += red[tid + s];
        __syncthreads();
    }
    float inv = 1.f / red[0];
#pragma unroll
    for (int j = 0; j < 9; j++) p[tid + j * 256] = loc[j] * inv;
}

// ---------------------------------------------------------------------------
// Launcher (graph-capturable: kernel launches only)
// ---------------------------------------------------------------------------
extern "C" void kernel_launch(void* const* d_in, const int* in_sizes, int n_in,
                              void* d_out, int out_size) {
    const float* hidden     = (const float*)d_in[0];
    const float* rope       = (const float*)d_in[1];
    const float* pre_norm_w = (const float*)d_in[2];
    const float* qkv_w      = (const float*)d_in[3];
    const float* q_norm_w   = (const float*)d_in[4];
    const float* k_norm_w   = (const float*)d_in[5];
    const float* proj_w     = (const float*)d_in[6];
    const int*   midsRaw    = (const int*)d_in[7];   // int32 OR int64, detected
    float*       out        = (float*)d_out;

    k_meta1<<<1, 256>>>(midsRaw);
    k_meta2<<<8, 256>>>(midsRaw);
    k_norm<<<NPAD, 256>>>(hidden, pre_norm_w);
    // QKV: C[2304, 7208] (N tiles = ceil(7208/128)=57)
    gemm_k<0><<<dim3(57, NPAD / 128, 1), 256>>>(qkv_w, nullptr, 0);
    k_qkvpost<<<NPAD, 256>>>(rope, q_norm_w, k_norm_w);
    // Attention in HCHUNK-head passes (g_s holds 4 heads)
    for (int c = 0; c < HKV / HCHUNK; c++) {
        int h0 = c * HCHUNK;
        // S = Q K^T: [11520, 2304] x4 heads
        gemm_k<1><<<dim3(NPAD / 128, MROWS / 128, HCHUNK), 256>>>(nullptr, nullptr, h0);
        k_softmax<<<HCHUNK * MROWS, 256>>>();
        // O = P V: [11520, 128] x4 heads (gated epilogue -> g_o)
        gemm_k<2><<<dim3(1, MROWS / 128, HCHUNK), 256>>>(nullptr, nullptr, h0);
    }
    // Projection + scatter to original token order
    gemm_k<3><<<dim3(HIDDEN / 128, NPAD / 128, 1), 256>>>(proj_w, out, 0);
}

// round 9
// speedup vs baseline: 1.6697x; 1.4467x over previous
#include <cuda_runtime.h>
#include <cuda_bf16.h>
#include <math.h>

// ---------------------------------------------------------------------------
// Problem constants
// ---------------------------------------------------------------------------
#define N_TOKS   2048
#define HIDDEN   5120
#define HEAD_DIM 128
#define HQ       40
#define HKV      8
#define NUM_MOD  3
#define Q_SIZE   5120           // HQ * HEAD_DIM
#define KV_SIZE  1024           // HKV * HEAD_DIM
#define GATE_N   40
#define QKV_OUT  7208           // Q_SIZE + 2*KV_SIZE + GATE_N
#define NPAD     2304           // max padded sorted rows (segments 128-aligned)
#define MROWS    (5 * NPAD)     // q-rows per kv head (group size 5) = 11520
#define HCHUNK   4              // kv heads processed per attention pass

// ---------------------------------------------------------------------------
// Scratch (static device globals; total ~655 MB)
// ---------------------------------------------------------------------------
__device__ float g_hnorm[(size_t)NPAD * HIDDEN];           // 47 MB
__device__ float g_qkv[(size_t)NPAD * QKV_OUT];            // 66 MB
__device__ float g_q[(size_t)HQ * NPAD * HEAD_DIM];        // 47 MB  [hq][r][d], hq = kv*5+g
__device__ float g_k[(size_t)HKV * NPAD * HEAD_DIM];       // 9.4 MB [kv][r][d]
__device__ float g_vt[(size_t)HKV * HEAD_DIM * NPAD];      // 9.4 MB [kv][d][r]  (transposed)
__device__ float g_s[(size_t)HCHUNK * MROWS * NPAD];       // 425 MB, 4 heads per pass
__device__ float g_o[(size_t)NPAD * Q_SIZE];               // 47 MB
__device__ float g_gate[NPAD * HQ];
__device__ int   g_rowMod[NPAD];
__device__ int   g_valid[NPAD];
__device__ int   g_srcTok[NPAD];
__device__ int   g_segStart[NUM_MOD + 1];
__device__ int   g_is64;

// Dtype-robust modality read (mids may be int32 or int64; detected at runtime).
__device__ __forceinline__ int getMid(const int* raw, int i, int is64) {
    return is64 ? (int)(reinterpret_cast<const long long*>(raw)[i]) : raw[i];
}

// ---------------------------------------------------------------------------
// Metadata kernels: deterministic modality sort (segments 128-aligned)
// ---------------------------------------------------------------------------
__global__ void k_meta1(const int* __restrict__ midsRaw) {
    __shared__ int cnt[NUM_MOD];
    __shared__ int sstart[NUM_MOD + 1];
    __shared__ int oddNZ;
    int tid = threadIdx.x;
    if (tid == 0) oddNZ = 0;
    if (tid < NUM_MOD) cnt[tid] = 0;
    __syncthreads();
    // int64 data has zero high-words at odd int32 positions; int32 data doesn't.
    for (int i = tid; i < N_TOKS / 2; i += blockDim.x)
        if (midsRaw[2 * i + 1] != 0) atomicExch(&oddNZ, 1);
    __syncthreads();
    int is64 = (oddNZ == 0);
    if (tid == 0) g_is64 = is64;

    for (int i = tid; i < N_TOKS; i += blockDim.x)
        atomicAdd(&cnt[getMid(midsRaw, i, is64)], 1);
    __syncthreads();
    if (tid == 0) {
        int s = 0;
        for (int m = 0; m < NUM_MOD; m++) {
            sstart[m] = s;
            g_segStart[m] = s;
            s += (cnt[m] + 127) & ~127;
        }
        sstart[NUM_MOD] = s;
        g_segStart[NUM_MOD] = s;
    }
    __syncthreads();
    for (int r = tid; r < NPAD; r += blockDim.x) {
        int mod = 0;
        if (r >= sstart[1]) mod = 1;
        if (r >= sstart[2]) mod = 2;
        if (r >= sstart[3]) mod = 0;   // tail beyond actual padded length
        g_rowMod[r] = mod;
        g_valid[r]  = 0;
        g_srcTok[r] = 0;
    }
}

// Deterministic rank: token i's slot = segStart[m] + #{j<i : mid[j]==m}
__global__ void k_meta2(const int* __restrict__ midsRaw) {
    int i = blockIdx.x * blockDim.x + threadIdx.x;
    if (i >= N_TOKS) return;
    int is64 = g_is64;
    int m = getMid(midsRaw, i, is64);
    int rank = 0;
    for (int j = 0; j < i; j++) rank += (getMid(midsRaw, j, is64) == m);
    int pos = g_segStart[m] + rank;
    g_srcTok[pos] = i;
    g_valid[pos]  = 1;
}

// ---------------------------------------------------------------------------
// Pre-norm RMSNorm + gather into sorted order (pads -> zeros)
// ---------------------------------------------------------------------------
__global__ void k_norm(const float* __restrict__ hidden,
                       const float* __restrict__ pnw) {
    int r = blockIdx.x, tid = threadIdx.x;
    int vld = g_valid[r];
    int src = g_srcTok[r];
    int mod = g_rowMod[r];
    const float4* x   = reinterpret_cast<const float4*>(hidden + (size_t)src * HIDDEN);
    const float4* w   = reinterpret_cast<const float4*>(pnw + mod * HIDDEN);
    float4*       out = reinterpret_cast<float4*>(g_hnorm + (size_t)r * HIDDEN);

    float ss = 0.f;
    if (vld) {
        for (int i = tid; i < HIDDEN / 4; i += blockDim.x) {
            float4 v = x[i];
            ss += v.x * v.x + v.y * v.y + v.z * v.z + v.w * v.w;
        }
    }
    __shared__ float red[256];
    red[tid] = ss;
    __syncthreads();
    for (int s = 128; s > 0; s >>= 1) {
        if (tid < s) red[tid] += red[tid + s];
        __syncthreads();
    }
    float rms = rsqrtf(red[0] / (float)HIDDEN + 1e-6f);
    if (vld) {
        for (int i = tid; i < HIDDEN / 4; i += blockDim.x) {
            float4 v = x[i], ww = w[i];
            out[i] = make_float4(v.x * rms * (ww.x + 1.f),
                                 v.y * rms * (ww.y + 1.f),
                                 v.z * rms * (ww.z + 1.f),
                                 v.w * rms * (ww.w + 1.f));
        }
    } else {
        float4 z = make_float4(0.f, 0.f, 0.f, 0.f);
        for (int i = tid; i < HIDDEN / 4; i += blockDim.x) out[i] = z;
    }
}

// ---------------------------------------------------------------------------
// 3xBF16 tensor-core GEMM, double-buffered smem pipeline.
// C[m,n] = sum_k A[m,k] * B[n,k]   (both row-major with K contiguous)
// Each operand split x = hi + lo (bf16 each, ~16 mantissa bits combined);
// acc += aH*bH + aH*bL + aL*bH  (fp32 accumulate; dropped aL*bL ~ 2^-18 rel).
// Tile 128x128x16, 256 threads, 8 warps (2 warp-rows x 4 warp-cols),
// each warp 64x32 via 4x4 m16n8k16 fragments, 3 mmas per fragment pair.
// smem words pack two bf16 k-values: [stage][hi/lo][kpair(8)][m(136 pad)].
// One __syncthreads per k16-slab; next slab's LDG overlaps current MMAs.
// MODE 0: QKV   A=g_hnorm          B=qkv_w[mod]    C=g_qkv    (N=7208 guard)
// MODE 1: S     A=g_q[head]        B=g_k[head]     C=g_s[chunk slot]
// MODE 2: O=PV  A=g_s[chunk slot]  B=g_vt[head]    C=g_o (gated epilogue)
// MODE 3: PROJ  A=g_o              B=proj_w[mod]   C=d_out (scatter rows)
// Modes 1/2: head = z + blockIdx.z, chunk slot = blockIdx.z.
// ---------------------------------------------------------------------------
__device__ __forceinline__ void split2_bf16(float x0, float x1,
                                            unsigned& hi, unsigned& lo) {
    __nv_bfloat16 h0 = __float2bfloat16_rn(x0);
    __nv_bfloat16 h1 = __float2bfloat16_rn(x1);
    __nv_bfloat16 l0 = __float2bfloat16_rn(x0 - __bfloat162float(h0));
    __nv_bfloat16 l1 = __float2bfloat16_rn(x1 - __bfloat162float(h1));
    hi = ((unsigned)__bfloat16_as_ushort(h1) << 16) | __bfloat16_as_ushort(h0);
    lo = ((unsigned)__bfloat16_as_ushort(l1) << 16) | __bfloat16_as_ushort(l0);
}
__device__ __forceinline__ void mma16(float* c, unsigned a0, unsigned a1,
                                      unsigned a2, unsigned a3,
                                      unsigned b0, unsigned b1) {
    asm volatile(
        "mma.sync.aligned.m16n8k16.row.col.f32.bf16.bf16.f32 "
        "{%0,%1,%2,%3}, {%4,%5,%6,%7}, {%8,%9}, {%0,%1,%2,%3};"
        : "+f"(c[0]), "+f"(c[1]), "+f"(c[2]), "+f"(c[3])
        : "r"(a0), "r"(a1), "r"(a2), "r"(a3), "r"(b0), "r"(b1));
}

template <int MODE>
__global__ __launch_bounds__(256) void gemm_k(const float* __restrict__ Bw,
                                              float* __restrict__ Cout,
                                              int z) {
    constexpr int KD   = (MODE == 0) ? HIDDEN : (MODE == 1) ? HEAD_DIM
                       : (MODE == 2) ? NPAD   : Q_SIZE;
    constexpr int NACT = (MODE == 0) ? QKV_OUT : (MODE == 1) ? NPAD
                       : (MODE == 2) ? HEAD_DIM : HIDDEN;
    constexpr int NK = KD / 16;

    __shared__ unsigned Ast[2][2][8][136];   // [stage][hi/lo][kpair][m]; 34.8 KB
    __shared__ unsigned Bst[2][2][8][136];

    const int tid   = threadIdx.x;
    const int tileN = blockIdx.x * 128;
    const int tileM = blockIdx.y * 128;
    const int zz    = z + blockIdx.z;                        // head (modes 1/2)
    const size_t sbase = (size_t)blockIdx.z * MROWS * NPAD;  // g_s slot (modes 1/2)

    const float* A;
    const float* B;
    if constexpr (MODE == 0) {
        A = g_hnorm;
        B = Bw + (size_t)g_rowMod[tileM] * ((size_t)QKV_OUT * HIDDEN);
    } else if constexpr (MODE == 1) {
        A = g_q + (size_t)zz * 5 * NPAD * HEAD_DIM;
        B = g_k + (size_t)zz * NPAD * HEAD_DIM;
    } else if constexpr (MODE == 2) {
        A = g_s + sbase;
        B = g_vt + (size_t)zz * HEAD_DIM * NPAD;
    } else {
        A = g_o;
        B = Bw + (size_t)g_rowMod[tileM] * ((size_t)HIDDEN * Q_SIZE);
    }

    const int rowL = tid >> 1;           // 0..127
    const int cg   = tid & 1;            // k-half (8 floats each)
    const int lane = tid & 31, warp = tid >> 5;
    const int gid = lane >> 2, tig = lane & 3;
    const int wm = (warp & 1) * 64, wn = (warp >> 1) * 32;

    float acc[4][4][4];
#pragma unroll
    for (int i = 0; i < 4; i++)
#pragma unroll
        for (int j = 0; j < 4; j++)
#pragma unroll
            for (int e = 0; e < 4; e++) acc[i][j][e] = 0.f;

    float4 av0, av1, bv0, bv1;
    const float4 zero4 = make_float4(0.f, 0.f, 0.f, 0.f);

#define LOAD_STAGE(kt)                                                          \
    do {                                                                        \
        int k0 = (kt)*16 + cg * 8;                                              \
        const float* ap = A + (size_t)(tileM + rowL) * KD + k0;                 \
        av0 = *reinterpret_cast<const float4*>(ap);                             \
        av1 = *reinterpret_cast<const float4*>(ap + 4);                         \
        int n0 = tileN + rowL;                                                  \
        if (n0 < NACT) {                                                        \
            const float* bp = B + (size_t)n0 * KD + k0;                         \
            bv0 = *reinterpret_cast<const float4*>(bp);                         \
            bv1 = *reinterpret_cast<const float4*>(bp + 4);                     \
        } else {                                                                \
            bv0 = zero4; bv1 = zero4;                                           \
        }                                                                       \
    } while (0)

#define STORE_STAGE(st)                                                         \
    do {                                                                        \
        unsigned h, l;                                                          \
        split2_bf16(av0.x, av0.y, h, l); Ast[st][0][cg*4+0][rowL] = h; Ast[st][1][cg*4+0][rowL] = l; \
        split2_bf16(av0.z, av0.w, h, l); Ast[st][0][cg*4+1][rowL] = h; Ast[st][1][cg*4+1][rowL] = l; \
        split2_bf16(av1.x, av1.y, h, l); Ast[st][0][cg*4+2][rowL] = h; Ast[st][1][cg*4+2][rowL] = l; \
        split2_bf16(av1.z, av1.w, h, l); Ast[st][0][cg*4+3][rowL] = h; Ast[st][1][cg*4+3][rowL] = l; \
        split2_bf16(bv0.x, bv0.y, h, l); Bst[st][0][cg*4+0][rowL] = h; Bst[st][1][cg*4+0][rowL] = l; \
        split2_bf16(bv0.z, bv0.w, h, l); Bst[st][0][cg*4+1][rowL] = h; Bst[st][1][cg*4+1][rowL] = l; \
        split2_bf16(bv1.x, bv1.y, h, l); Bst[st][0][cg*4+2][rowL] = h; Bst[st][1][cg*4+2][rowL] = l; \
        split2_bf16(bv1.z, bv1.w, h, l); Bst[st][0][cg*4+3][rowL] = h; Bst[st][1][cg*4+3][rowL] = l; \
    } while (0)

    LOAD_STAGE(0);
    STORE_STAGE(0);
    __syncthreads();
    for (int kt = 0; kt < NK; kt++) {
        const int cur = kt & 1;
        const bool more = (kt + 1 < NK);
        if (more) LOAD_STAGE(kt + 1);   // LDG latency hidden under the MMAs below

        unsigned aH[4][4], aL[4][4], bH[4][2], bL[4][2];
#pragma unroll
        for (int mi = 0; mi < 4; mi++) {
            int m0 = wm + mi * 16 + gid;
            aH[mi][0] = Ast[cur][0][tig][m0];     aL[mi][0] = Ast[cur][1][tig][m0];
            aH[mi][1] = Ast[cur][0][tig][m0 + 8]; aL[mi][1] = Ast[cur][1][tig][m0 + 8];
            aH[mi][2] = Ast[cur][0][tig + 4][m0]; aL[mi][2] = Ast[cur][1][tig + 4][m0];
            aH[mi][3] = Ast[cur][0][tig + 4][m0 + 8]; aL[mi][3] = Ast[cur][1][tig + 4][m0 + 8];
        }
#pragma unroll
        for (int ni = 0; ni < 4; ni++) {
            int n0 = wn + ni * 8 + gid;
            bH[ni][0] = Bst[cur][0][tig][n0];     bL[ni][0] = Bst[cur][1][tig][n0];
            bH[ni][1] = Bst[cur][0][tig + 4][n0]; bL[ni][1] = Bst[cur][1][tig + 4][n0];
        }
#pragma unroll
        for (int mi = 0; mi < 4; mi++)
#pragma unroll
            for (int ni = 0; ni < 4; ni++) {
                mma16(acc[mi][ni], aH[mi][0], aH[mi][1], aH[mi][2], aH[mi][3],
                      bH[ni][0], bH[ni][1]);
                mma16(acc[mi][ni], aH[mi][0], aH[mi][1], aH[mi][2], aH[mi][3],
                      bL[ni][0], bL[ni][1]);
                mma16(acc[mi][ni], aL[mi][0], aL[mi][1], aL[mi][2], aL[mi][3],
                      bH[ni][0], bH[ni][1]);
            }
        if (more) STORE_STAGE(cur ^ 1);
        __syncthreads();
    }
#undef LOAD_STAGE
#undef STORE_STAGE

    // Epilogue: c0/c1 -> (r0, c0..c0+1), c2/c3 -> (r0+8, same cols)
#pragma unroll
    for (int mi = 0; mi < 4; mi++) {
#pragma unroll
        for (int ni = 0; ni < 4; ni++) {
            int r0 = tileM + wm + mi * 16 + gid;
            int c0 = tileN + wn + ni * 8 + tig * 2;
            float* cc = acc[mi][ni];
            if constexpr (MODE == 0) {
                if (c0 < QKV_OUT) {
                    *(float2*)&g_qkv[(size_t)r0 * QKV_OUT + c0] =
                        make_float2(cc[0], cc[1]);
                    *(float2*)&g_qkv[(size_t)(r0 + 8) * QKV_OUT + c0] =
                        make_float2(cc[2], cc[3]);
                }
            } else if constexpr (MODE == 1) {
                *(float2*)&g_s[sbase + (size_t)r0 * NPAD + c0] =
                    make_float2(cc[0], cc[1]);
                *(float2*)&g_s[sbase + (size_t)(r0 + 8) * NPAD + c0] =
                    make_float2(cc[2], cc[3]);
            } else if constexpr (MODE == 2) {
#pragma unroll
                for (int e = 0; e < 4; e++) {
                    int r   = r0 + ((e >= 2) ? 8 : 0);
                    int col = c0 + (e & 1);
                    int gq  = r / NPAD;
                    int rr  = r - gq * NPAD;
                    int hq  = zz * 5 + gq;
                    float gv  = g_gate[rr * HQ + hq];
                    float sig = 1.f / (1.f + __expf(-gv));
                    g_o[(size_t)rr * Q_SIZE + hq * HEAD_DIM + col] = cc[e] * sig;
                }
            } else {
                if (g_valid[r0])
                    *(float2*)&Cout[(size_t)g_srcTok[r0] * HIDDEN + c0] =
                        make_float2(cc[0], cc[1]);
                if (g_valid[r0 + 8])
                    *(float2*)&Cout[(size_t)g_srcTok[r0 + 8] * HIDDEN + c0] =
                        make_float2(cc[2], cc[3]);
            }
        }
    }
}

// ---------------------------------------------------------------------------
// QKV post-processing: per-head RMSNorm (q,k) + RoPE + q-scale,
// V transpose into [kv][d][r], gate stash. One block per sorted row.
// ---------------------------------------------------------------------------
__global__ void k_qkvpost(const float* __restrict__ rope,
                          const float* __restrict__ qnw,
                          const float* __restrict__ knw) {
    int r = blockIdx.x, tid = threadIdx.x;
    int src = g_srcTok[r];
    int mod = g_rowMod[r];
    __shared__ float sn[64], sc[64];
    if (tid < 64)       sn[tid]      = rope[(size_t)src * HEAD_DIM + tid];
    else if (tid < 128) sc[tid - 64] = rope[(size_t)src * HEAD_DIM + tid];
    const float* row = g_qkv + (size_t)r * QKV_OUT;
    __syncthreads();

    int lane = tid & 31, warp = tid >> 5;
    for (int hh = warp; hh < HQ + HKV; hh += 8) {
        const float* xp;
        const float* wp;
        if (hh < HQ) { xp = row + hh * HEAD_DIM;                 wp = qnw + mod * HEAD_DIM; }
        else         { xp = row + Q_SIZE + (hh - HQ) * HEAD_DIM; wp = knw + mod * HEAD_DIM; }
        float x0 = xp[lane], x1 = xp[lane + 32], x2 = xp[lane + 64], x3 = xp[lane + 96];
        float ssq = x0 * x0 + x1 * x1 + x2 * x2 + x3 * x3;
#pragma unroll
        for (int o = 16; o > 0; o >>= 1) ssq += __shfl_xor_sync(0xffffffffu, ssq, o);
        float rms = rsqrtf(ssq / (float)HEAD_DIM + 1e-6f);
        float y0 = x0 * rms * (wp[lane] + 1.f);
        float y1 = x1 * rms * (wp[lane + 32] + 1.f);
        float y2 = x2 * rms * (wp[lane + 64] + 1.f);
        float y3 = x3 * rms * (wp[lane + 96] + 1.f);
        float c0 = sc[lane], s0 = sn[lane];
        float c1 = sc[lane + 32], s1 = sn[lane + 32];
        float o0 = y0 * c0 - y2 * s0;
        float o2 = y0 * s0 + y2 * c0;
        float o1 = y1 * c1 - y3 * s1;
        float o3 = y1 * s1 + y3 * c1;
        if (hh < HQ) {
            const float scl = 0.08838834764831845f;  // 1/sqrt(128), folded into q
            float* q = g_q + ((size_t)hh * NPAD + r) * HEAD_DIM;
            q[lane] = o0 * scl; q[lane + 32] = o1 * scl;
            q[lane + 64] = o2 * scl; q[lane + 96] = o3 * scl;
        } else {
            float* k = g_k + ((size_t)(hh - HQ) * NPAD + r) * HEAD_DIM;
            k[lane] = o0; k[lane + 32] = o1; k[lane + 64] = o2; k[lane + 96] = o3;
        }
    }
    // V transpose: g_vt[kv][d][r] = v[r][kv][d]
    for (int idx = tid; idx < HKV * HEAD_DIM; idx += blockDim.x) {
        int kh = idx >> 7, d = idx & 127;
        g_vt[((size_t)kh * HEAD_DIM + d) * NPAD + r] = row[Q_SIZE + KV_SIZE + idx];
    }
    if (tid < HQ) g_gate[r * HQ + tid] = row[Q_SIZE + 2 * KV_SIZE + tid];
}

// ---------------------------------------------------------------------------
// Masked softmax over key dim (width NPAD = 2304 = 9*256); P overwrites S.
// Grid covers HCHUNK * MROWS rows of the 4-head g_s buffer.
// ---------------------------------------------------------------------------
__global__ void k_softmax() {
    int tid  = threadIdx.x;
    float* p = g_s + (size_t)blockIdx.x * NPAD;
    float loc[9];
    float mx = -1e30f;
#pragma unroll
    for (int j = 0; j < 9; j++) {
        int c = tid + j * 256;
        float v = g_valid[c] ? p[c] : -1e30f;
        loc[j] = v;
        mx = fmaxf(mx, v);
    }
    __shared__ float red[256];
    red[tid] = mx;
    __syncthreads();
    for (int s = 128; s > 0; s >>= 1) {
        if (tid < s) red[tid] = fmaxf(red[tid], red[tid + s]);
        __syncthreads();
    }
    float m = red[0];
    __syncthreads();
    float sum = 0.f;
#pragma unroll
    for (int j = 0; j < 9; j++) {
        float e = (loc[j] > -1e29f) ? __expf(loc[j] - m) : 0.f;
        loc[j] = e;
        sum += e;
    }
    red[tid] = sum;
    __syncthreads();
    for (int s = 128; s > 0; s >>= 1) {
        if (tid < s) red[tid] += red[tid + s];
        __syncthreads();
    }
    float inv = 1.f / red[0];
#pragma unroll
    for (int j = 0; j < 9; j++) p[tid + j * 256] = loc[j] * inv;
}

// ---------------------------------------------------------------------------
// Launcher (graph-capturable: kernel launches only)
// ---------------------------------------------------------------------------
extern "C" void kernel_launch(void* const* d_in, const int* in_sizes, int n_in,
                              void* d_out, int out_size) {
    const float* hidden     = (const float*)d_in[0];
    const float* rope       = (const float*)d_in[1];
    const float* pre_norm_w = (const float*)d_in[2];
    const float* qkv_w      = (const float*)d_in[3];
    const float* q_norm_w   = (const float*)d_in[4];
    const float* k_norm_w   = (const float*)d_in[5];
    const float* proj_w     = (const float*)d_in[6];
    const int*   midsRaw    = (const int*)d_in[7];   // int32 OR int64, detected
    float*       out        = (float*)d_out;

    k_meta1<<<1, 256>>>(midsRaw);
    k_meta2<<<8, 256>>>(midsRaw);
    k_norm<<<NPAD, 256>>>(hidden, pre_norm_w);
    // QKV: C[2304, 7208] (N tiles = ceil(7208/128)=57)
    gemm_k<0><<<dim3(57, NPAD / 128, 1), 256>>>(qkv_w, nullptr, 0);
    k_qkvpost<<<NPAD, 256>>>(rope, q_norm_w, k_norm_w);
    // Attention in HCHUNK-head passes (g_s holds 4 heads)
    for (int c = 0; c < HKV / HCHUNK; c++) {
        int h0 = c * HCHUNK;
        // S = Q K^T: [11520, 2304] x4 heads
        gemm_k<1><<<dim3(NPAD / 128, MROWS / 128, HCHUNK), 256>>>(nullptr, nullptr, h0);
        k_softmax<<<HCHUNK * MROWS, 256>>>();
        // O = P V: [11520, 128] x4 heads (gated epilogue -> g_o)
        gemm_k<2><<<dim3(1, MROWS / 128, HCHUNK), 256>>>(nullptr, nullptr, h0);
    }
    // Projection + scatter to original token order
    gemm_k<3><<<dim3(HIDDEN / 128, NPAD / 128, 1), 256>>>(proj_w, out, 0);
}